// round 13
// baseline (speedup 1.0000x reference)
#include <cuda_runtime.h>
#include <cstdint>
#include <math.h>

#define DEV_INLINE __device__ __forceinline__

constexpr int B_   = 4;
constexpr int C_   = 256;
constexpr int N_   = 16384;
constexpr int BN_  = B_ * N_;
constexpr int H1   = 64;
constexpr int NCLS = 10;
constexpr int NQ   = 256;

constexpr long long OFF_QUERY = 0;
constexpr long long OFF_QF    = 3072;
constexpr long long OFF_PREDS = 265216;
constexpr long long OFF_M     = 265256;
constexpr long long OFF_G0    = 17042472;
constexpr long long OFF_G1    = 17075240;

__device__ float  g_y[(size_t)BN_ * H1];
__device__ float  g_mpre[(size_t)B_ * C_ * N_];
__device__ float  g_srep[(size_t)BN_];
__device__ float  g_expv[(size_t)BN_];
__device__ double g_summ[C_], g_sqm[C_];
__device__ double g_psum[B_ * NCLS];
__device__ float  g_mean1[H1], g_rstd1[H1], g_meanm[C_], g_rstdm[C_];
__device__ int    g_label[B_];
__device__ int    g_qidx[B_ * NQ];
__device__ float  g_M32f[B_], g_L2f[B_];

DEV_INLINE unsigned long long pack2(float lo, float hi) {
    unsigned long long r;
    asm("mov.b64 %0, {%1, %2};" : "=l"(r) : "f"(lo), "f"(hi));
    return r;
}
DEV_INLINE void unpack2(unsigned long long v, float &lo, float &hi) {
    asm("mov.b64 {%0, %1}, %2;" : "=f"(lo), "=f"(hi) : "l"(v));
}
DEV_INLINE void fma2(unsigned long long &d, unsigned long long a, unsigned long long b) {
    asm("fma.rn.f32x2 %0, %1, %2, %0;" : "+l"(d) : "l"(a), "l"(b));
}

// XLA EmitFastTanh (f32), separate mul/add (no contraction in XLA:CPU IR)
DEV_INLINE float tanh_xla(float x) {
    if (fabsf(x) < 0.0004f) return x;
    float cx = fminf(fmaxf(x, -7.90531110763549805f), 7.90531110763549805f);
    float x2 = __fmul_rn(cx, cx);
    float p = -2.76076847742355e-16f;
    p = __fadd_rn(__fmul_rn(x2, p), 2.00018790482477e-13f);
    p = __fadd_rn(__fmul_rn(x2, p), -8.60467152213735e-11f);
    p = __fadd_rn(__fmul_rn(x2, p), 5.12229709037114e-08f);
    p = __fadd_rn(__fmul_rn(x2, p), 1.48572235717979e-05f);
    p = __fadd_rn(__fmul_rn(x2, p), 6.37261928875436e-04f);
    p = __fadd_rn(__fmul_rn(x2, p), 4.89352455891786e-03f);
    float num = __fmul_rn(cx, p);
    float q = 1.19825839466702e-06f;
    q = __fadd_rn(__fmul_rn(x2, q), 1.18534705686654e-04f);
    q = __fadd_rn(__fmul_rn(x2, q), 2.26843463243900e-03f);
    q = __fadd_rn(__fmul_rn(x2, q), 4.89352518554385e-03f);
    return __fdiv_rn(num, q);
}
// jax.nn.gelu approximate=True, op-for-op (x**3 = (x*x)*x)
DEV_INLINE float gelu_xla(float x) {
    float x2 = __fmul_rn(x, x);
    float x3 = __fmul_rn(x2, x);
    float t  = __fadd_rn(x, __fmul_rn(0.044715f, x3));
    float u  = __fmul_rn(0.7978845608028654f, t);
    float th = tanh_xla(u);
    float cdf = __fmul_rn(0.5f, __fadd_rn(1.0f, th));
    return __fmul_rn(x, cdf);
}

__global__ void init_k() {
    int t = threadIdx.x;
    if (t < C_)        { g_summ[t] = 0.0; g_sqm[t] = 0.0; }
    if (t < B_ * NCLS) g_psum[t] = 0.0;
}

// feats[b]^T @ W; block 128n x BJ j; pure ascending-k FMA chain (== Eigen bits)
template<int BJ, int TJ, int JT, int MODE>
__global__ __launch_bounds__(256) void gemm_k(const float* __restrict__ Aall,
                                              const float* __restrict__ W) {
    const int b  = blockIdx.z;
    const int n0 = blockIdx.x * 128;
    const int j0 = blockIdx.y * BJ;
    const float* Ab = Aall + (size_t)b * C_ * N_;
    __shared__ __align__(16) float As[16][128];
    __shared__ __align__(16) float Ws[16][BJ];
    const int tid = threadIdx.x;
    const int tx  = tid & 15;
    const int ty  = tid >> 4;
    unsigned long long acc[4][TJ];
#pragma unroll
    for (int p = 0; p < 4; p++)
#pragma unroll
        for (int jj = 0; jj < TJ; jj++) acc[p][jj] = 0ull;

    for (int k0 = 0; k0 < C_; k0 += 16) {
#pragma unroll
        for (int l = 0; l < 2; l++) {
            int e = tid + l * 256;
            int rr = e >> 5, c4 = e & 31;
            ((float4*)As)[e] = *(const float4*)(Ab + (size_t)(k0 + rr) * N_ + n0 + c4 * 4);
        }
        if (BJ == 128) {
#pragma unroll
            for (int l = 0; l < 2; l++) {
                int e = tid + l * 256;
                int rr = e >> 5, c4 = e & 31;
                ((float4*)Ws)[e] = *(const float4*)(W + (k0 + rr) * JT + j0 + c4 * 4);
            }
        } else {
            int rr = tid >> 4, c4 = tid & 15;
            ((float4*)Ws)[tid] = *(const float4*)(W + (k0 + rr) * JT + j0 + c4 * 4);
        }
        __syncthreads();
#pragma unroll
        for (int k = 0; k < 16; k++) {
            unsigned long long a2[4];
#pragma unroll
            for (int p = 0; p < 4; p++)
                a2[p] = *(const unsigned long long*)&As[k][ty * 8 + 2 * p];
#pragma unroll
            for (int jj = 0; jj < TJ; jj++) {
                float bv = Ws[k][tx + 16 * jj];
                unsigned long long b2 = pack2(bv, bv);
#pragma unroll
                for (int p = 0; p < 4; p++) fma2(acc[p][jj], a2[p], b2);
            }
        }
        __syncthreads();
    }
    if (MODE == 0) {
#pragma unroll
        for (int jj = 0; jj < TJ; jj++) {
            int j = j0 + tx + 16 * jj;
#pragma unroll
            for (int p = 0; p < 4; p++) {
                float lo, hi; unpack2(acc[p][jj], lo, hi);
                int n = n0 + ty * 8 + 2 * p;
                g_y[(size_t)(b * N_ + n) * JT + j]     = lo;
                g_y[(size_t)(b * N_ + n + 1) * JT + j] = hi;
            }
        }
    } else {
#pragma unroll
        for (int jj = 0; jj < TJ; jj++) {
            int j = j0 + tx + 16 * jj;
            float v[8];
#pragma unroll
            for (int p = 0; p < 4; p++) unpack2(acc[p][jj], v[2 * p], v[2 * p + 1]);
            float* dst = g_mpre + (size_t)(b * JT + j) * N_ + n0 + ty * 8;
            ((float4*)dst)[0] = make_float4(v[0], v[1], v[2], v[3]);
            ((float4*)dst)[1] = make_float4(v[4], v[5], v[6], v[7]);
        }
    }
}

// sequential fp32 chains over all BN rows ascending (XLA:CPU scalar reduce)
__global__ void meanchain_k() {
    int j = threadIdx.x;  // 64
    float acc = 0.f;
    const float* p = g_y + j;
#pragma unroll 16
    for (int r = 0; r < BN_; r++) acc = __fadd_rn(acc, __ldg(&p[(size_t)r * H1]));
    g_mean1[j] = acc / 65536.0f;   // exact
}
__global__ void varchain_k() {
    int j = threadIdx.x;
    float m = g_mean1[j];
    float acc = 0.f;
    const float* p = g_y + j;
#pragma unroll 16
    for (int r = 0; r < BN_; r++) {
        float d = __fadd_rn(__ldg(&p[(size_t)r * H1]), -m);
        acc = __fadd_rn(acc, __fmul_rn(d, d));
    }
    float var = acc / 65536.0f;
    g_rstd1[j] = __fdiv_rn(1.0f, __fsqrt_rn(__fadd_rn(var, 1e-5f)));
}

// preds + label (tolerance path)
__global__ __launch_bounds__(256) void heat_k(const float* __restrict__ g1,
                                              const float* __restrict__ b1,
                                              const float* __restrict__ w2) {
    int tid = threadIdx.x;
    int r   = blockIdx.x * 256 + tid;
    int b   = r >> 14;
    __shared__ float sw2[H1 * NCLS];
    __shared__ float sm[H1], sr[H1], sg[H1], sb[H1];
    __shared__ float sps[NCLS];
    for (int i = tid; i < H1 * NCLS; i += 256) sw2[i] = w2[i];
    if (tid < H1) { sm[tid] = g_mean1[tid]; sr[tid] = g_rstd1[tid]; sg[tid] = g1[tid]; sb[tid] = b1[tid]; }
    if (tid < NCLS) sps[tid] = 0.f;
    __syncthreads();
    float acc[NCLS];
#pragma unroll
    for (int c = 0; c < NCLS; c++) acc[c] = 0.f;
    const float4* yr = (const float4*)(g_y + (size_t)r * H1);
#pragma unroll
    for (int t = 0; t < 16; t++) {
        float4 v4 = yr[t];
        float vv[4] = {v4.x, v4.y, v4.z, v4.w};
#pragma unroll
        for (int e = 0; e < 4; e++) {
            int j = 4 * t + e;
            float hv = gelu_xla((vv[e] - sm[j]) * sr[j] * sg[j] + sb[j]);
#pragma unroll
            for (int c = 0; c < NCLS; c++) acc[c] += hv * sw2[j * NCLS + c];
        }
    }
    int lane = tid & 31;
#pragma unroll
    for (int c = 0; c < NCLS; c++) {
        float v = acc[c];
        for (int o = 16; o > 0; o >>= 1) v += __shfl_down_sync(0xffffffffu, v, o);
        if (lane == 0) atomicAdd(&sps[c], v);
    }
    __syncthreads();
    if (tid < NCLS) atomicAdd(&g_psum[b * NCLS + tid], (double)sps[tid]);
}

__global__ void fin2_k(float* __restrict__ out) {
    int t = threadIdx.x;
    if (t < B_ * NCLS) out[OFF_PREDS + t] = (float)(g_psum[t] / (double)N_);
    if (t < B_) {
        double best = -1e300; int bi = 0;
        for (int c = 0; c < NCLS; c++) {
            double v = g_psum[t * NCLS + c];
            if (v > best) { best = v; bi = c; }
        }
        g_label[t] = bi;
    }
}

// exact replicated label scores: BN ops separate, XLA gelu, ascending-j fmaf chain
__global__ __launch_bounds__(256) void srep_k(const float* __restrict__ g1,
                                              const float* __restrict__ b1,
                                              const float* __restrict__ w2) {
    int n = blockIdx.x * 256 + threadIdx.x;
    int b = blockIdx.y;
    int label = g_label[b];
    const float* yr = g_y + (size_t)(b * N_ + n) * H1;
    float acc = 0.0f;
#pragma unroll 4
    for (int j = 0; j < H1; j++) {
        float d  = __fadd_rn(yr[j], -g_mean1[j]);
        float z  = __fmul_rn(d, g_rstd1[j]);
        float z2 = __fmul_rn(z, __ldg(&g1[j]));
        float z3 = __fadd_rn(z2, __ldg(&b1[j]));
        float h  = gelu_xla(z3);
        acc = __fmaf_rn(h, __ldg(&w2[j * NCLS + label]), acc);
    }
    g_srep[b * N_ + n] = acc;
}

__global__ __launch_bounds__(256) void mmax_k() {
    int b = blockIdx.x, tid = threadIdx.x;
    float m = -3.0e38f;
    for (int n = tid; n < N_; n += 256) m = fmaxf(m, g_srep[b * N_ + n]);
    __shared__ float red[256];
    red[tid] = m;
    __syncthreads();
    for (int off = 128; off > 0; off >>= 1) {
        if (tid < off) red[tid] = fmaxf(red[tid], red[tid + off]);
        __syncthreads();
    }
    if (tid == 0) g_M32f[b] = red[0];
}

__global__ __launch_bounds__(256) void expprep_k() {
    int n = blockIdx.x * 256 + threadIdx.x;
    int b = blockIdx.y;
    float a = __fadd_rn(g_srep[b * N_ + n], -g_M32f[b]);
    g_expv[b * N_ + n] = (float)exp((double)a);   // CR fp32 exp
}

__global__ void sumchain_k() {
    int b = threadIdx.x;
    if (b >= B_) return;
    const float* e = g_expv + b * N_;
    float acc = 0.f;
#pragma unroll 16
    for (int n = 0; n < N_; n++) acc = __fadd_rn(acc, __ldg(&e[n]));
    g_L2f[b] = (float)log((double)acc);           // CR fp32 log (±1ulp tie-invariant)
}

DEV_INLINE unsigned long long okey(float s, int n) {
    unsigned u = __float_as_uint(s);
    u = (u & 0x80000000u) ? ~u : (u | 0x80000000u);
    return ((unsigned long long)u << 14) | (unsigned long long)(N_ - 1 - n);
}
DEV_INLINE unsigned long long lp_key(int b, int n) {
    float a  = __fadd_rn(g_srep[b * N_ + n], -g_M32f[b]);
    float lp = __fadd_rn(a, -g_L2f[b]);
    return okey(lp, n);
}

__global__ __launch_bounds__(256) void select_k() {
    int b = blockIdx.x, tid = threadIdx.x;
    __shared__ unsigned hist[256];
    __shared__ unsigned long long s_prefix;
    __shared__ int s_kth;
    __shared__ unsigned long long s_keys[NQ];
    __shared__ int s_cnt;
    if (tid == 0) { s_prefix = 0ull; s_kth = NQ; s_cnt = 0; }
    __syncthreads();
    const int shifts[6] = {38, 30, 22, 14, 6, 0};
    for (int pass = 0; pass < 6; pass++) {
        int width = (pass == 5) ? 6 : 8;
        int sh = shifts[pass];
        hist[tid] = 0u;
        __syncthreads();
        unsigned long long pfx = s_prefix;
        int topshift = sh + width;
        for (int n = tid; n < N_; n += 256) {
            unsigned long long k = lp_key(b, n);
            if ((k >> topshift) == pfx)
                atomicAdd(&hist[(unsigned)((k >> sh) & ((1u << width) - 1u))], 1u);
        }
        __syncthreads();
        if (tid == 0) {
            int kk = s_kth;
            for (int bin = (1 << width) - 1; bin >= 0; bin--) {
                int c = (int)hist[bin];
                if (kk <= c) { s_prefix = (pfx << width) | (unsigned)bin; s_kth = kk; break; }
                kk -= c;
            }
        }
        __syncthreads();
    }
    unsigned long long kmin = s_prefix;
    for (int n = tid; n < N_; n += 256) {
        unsigned long long k = lp_key(b, n);
        if (k >= kmin) {
            int p = atomicAdd(&s_cnt, 1);
            if (p < NQ) s_keys[p] = k;
        }
    }
    __syncthreads();
    unsigned long long k = s_keys[tid];
    int rank = 0;
    for (int j = 0; j < NQ; j++) rank += (s_keys[j] > k) ? 1 : 0;
    g_qidx[b * NQ + rank] = (N_ - 1) - (int)(k & 0x3FFFull);
}

__global__ void gather_k(const float* __restrict__ points,
                         const float* __restrict__ feats,
                         float* __restrict__ out) {
    int i = blockIdx.x * 256 + threadIdx.x;
    if (i < B_ * 3 * NQ) {
        int b = i / (3 * NQ);
        int rem = i - b * 3 * NQ;
        int kk = rem / NQ;
        int q = rem & (NQ - 1);
        int idx = g_qidx[b * NQ + q];
        out[OFF_QUERY + i] = points[(size_t)(b * 3 + kk) * N_ + idx];
    } else {
        int j = i - B_ * 3 * NQ;
        if (j < B_ * C_ * NQ) {
            int b = j >> 16;
            int c = (j >> 8) & 255;
            int q = j & 255;
            int idx = g_qidx[(b << 8) + q];
            out[OFF_QF + j] = feats[(size_t)(b * C_ + c) * N_ + idx];
        }
    }
}

__global__ __launch_bounds__(256) void statsm_k() {
    int blk = blockIdx.x;
    int d = blk & 255;
    const float4* p4 = (const float4*)(g_mpre + (size_t)blk * N_);
    float s = 0.f, q = 0.f;
#pragma unroll
    for (int kk = 0; kk < 16; kk++) {
        float4 v = p4[threadIdx.x + 256 * kk];
        s += v.x + v.y + v.z + v.w;
        q += v.x * v.x + v.y * v.y + v.z * v.z + v.w * v.w;
    }
    __shared__ float ss[256], sq[256];
    ss[threadIdx.x] = s; sq[threadIdx.x] = q;
    __syncthreads();
    for (int st = 128; st > 0; st >>= 1) {
        if (threadIdx.x < st) {
            ss[threadIdx.x] += ss[threadIdx.x + st];
            sq[threadIdx.x] += sq[threadIdx.x + st];
        }
        __syncthreads();
    }
    if (threadIdx.x == 0) {
        atomicAdd(&g_summ[d], (double)ss[0]);
        atomicAdd(&g_sqm[d], (double)sq[0]);
    }
}

__global__ void fin3_k() {
    int d = threadIdx.x;
    if (d < C_) {
        double m   = g_summ[d] / (double)BN_;
        double var = g_sqm[d] / (double)BN_ - m * m;
        g_meanm[d] = (float)m;
        float arg = (float)var + 1e-5f;
        g_rstdm[d] = __fdiv_rn(1.0f, __fsqrt_rn(arg));
    }
}

__global__ __launch_bounds__(256) void bngelu_k(const float* __restrict__ gm,
                                                const float* __restrict__ bm,
                                                float* __restrict__ out) {
    size_t i = (size_t)blockIdx.x * 256 + threadIdx.x;
    int d = (int)((i >> 14) & 255);
    float v = g_mpre[i];
    out[OFF_M + i] = gelu_xla((v - g_meanm[d]) * g_rstdm[d] * __ldg(&gm[d]) + __ldg(&bm[d]));
}

__global__ __launch_bounds__(256) void ball_k(const float* __restrict__ points,
                                              float* __restrict__ out) {
    int wid  = (blockIdx.x * 256 + threadIdx.x) >> 5;
    int lane = threadIdx.x & 31;
    int b = wid >> 8;
    const float* px = points + (size_t)b * 3 * N_;
    int qi = g_qidx[wid];
    float qx = __ldg(&px[qi]), qy = __ldg(&px[N_ + qi]), qz = __ldg(&px[2 * N_ + qi]);
    const float R0 = (float)(0.2 * 0.2), R1 = (float)(0.4 * 0.4);
    float* o0 = out + OFF_G0 + (size_t)wid * 32;
    float* o1 = out + OFF_G1 + (size_t)wid * 64;
    int c0 = 0, c1 = 0, first0 = -1, first1 = -1;
    unsigned ltm = (1u << lane) - 1u;
    for (int base = 0; base < N_; base += 32) {
        int n = base + lane;
        float dx = __fadd_rn(qx, -px[n]);
        float dy = __fadd_rn(qy, -px[N_ + n]);
        float dz = __fadd_rn(qz, -px[2 * N_ + n]);
        float d = __fadd_rn(__fadd_rn(__fmul_rn(dx, dx), __fmul_rn(dy, dy)), __fmul_rn(dz, dz));
        bool in0 = !(d > R0), in1 = !(d > R1);
        unsigned m0 = __ballot_sync(0xffffffffu, in0);
        unsigned m1 = __ballot_sync(0xffffffffu, in1);
        if (first0 < 0 && m0) first0 = base + __ffs(m0) - 1;
        if (first1 < 0 && m1) first1 = base + __ffs(m1) - 1;
        int p0 = c0 + __popc(m0 & ltm);
        int p1 = c1 + __popc(m1 & ltm);
        if (in0 && p0 < 32) o0[p0] = (float)n;
        if (in1 && p1 < 64) o1[p1] = (float)n;
        c0 += __popc(m0); c1 += __popc(m1);
        if (c0 >= 32 && c1 >= 64) break;
    }
    float f0 = (first0 >= 0) ? (float)first0 : (float)(N_ - 1);
    float f1 = (first1 >= 0) ? (float)first1 : (float)(N_ - 1);
    for (int kk = min(c0, 32) + lane; kk < 32; kk += 32) o0[kk] = f0;
    for (int kk = min(c1, 64) + lane; kk < 64; kk += 32) o1[kk] = f1;
}

extern "C" void kernel_launch(void* const* d_in, const int* in_sizes, int n_in,
                              void* d_out, int out_size) {
    const float* points = (const float*)d_in[0];
    const float* feats  = (const float*)d_in[1];
    const float* w1     = (const float*)d_in[2];
    const float* g1     = (const float*)d_in[3];
    const float* b1     = (const float*)d_in[4];
    const float* w2     = (const float*)d_in[5];
    const float* wm     = (const float*)d_in[6];
    const float* gm     = (const float*)d_in[7];
    const float* bm     = (const float*)d_in[8];
    float* out = (float*)d_out;

    init_k<<<1, 256>>>();
    gemm_k<64, 4, 64, 0><<<dim3(128, 1, B_), 256>>>(feats, w1);
    gemm_k<128, 8, 256, 1><<<dim3(128, 2, B_), 256>>>(feats, wm);
    meanchain_k<<<1, 64>>>();
    varchain_k<<<1, 64>>>();
    heat_k<<<256, 256>>>(g1, b1, w2);
    fin2_k<<<1, 64>>>(out);
    srep_k<<<dim3(N_ / 256, B_), 256>>>(g1, b1, w2);
    mmax_k<<<B_, 256>>>();
    expprep_k<<<dim3(N_ / 256, B_), 256>>>();
    sumchain_k<<<1, 32>>>();
    select_k<<<B_, 256>>>();
    gather_k<<<1036, 256>>>(points, feats, out);
    statsm_k<<<B_ * C_, 256>>>();
    fin3_k<<<1, 256>>>();
    bngelu_k<<<(B_ * C_ * N_) / 256, 256>>>(gm, bm, out);
    ball_k<<<(B_ * NQ) / 8, 256>>>(points, out);
}